// round 6
// baseline (speedup 1.0000x reference)
#include <cuda_runtime.h>
#include <float.h>
#include <stdint.h>

#define N_SAMPLES 8192
#define DIM 128
#define N_EMBED 10000
#define N_EMBED_PAD 10240
#define TN 128
#define TM 128
#define THREADS 512
#define NSLICE 16
#define SLICE_W 640           // clusters per slice
#define NCH 5                 // chunks of TN per slice

typedef unsigned long long u64;

// Padded cluster norms; entries >= N_EMBED are -1e30 so they never win argmax.
__device__ float g_cnorm[N_EMBED_PAD];
// Per-sample packed (encoded_val << 32 | ~j); atomicMax-merged across slices.
__device__ u64 g_best[N_SAMPLES];

// 160 blocks x 256 threads: 64 j's per block, 4-way d-split + smem reduce.
__global__ void cnorm_kernel(const float* __restrict__ cm) {
    __shared__ float red[4][64];
    const int tid = threadIdx.x;
    const int jl  = tid & 63;
    const int dc  = tid >> 6;            // 0..3 -> d range [32*dc, 32*dc+32)
    const int j   = blockIdx.x * 64 + jl;

    const int gid = blockIdx.x * 256 + tid;
    if (gid < N_SAMPLES) g_best[gid] = 0ull;

    float s = 0.f;
    if (j < N_EMBED) {
#pragma unroll 8
        for (int dd = 0; dd < 32; dd++) {
            float v = cm[(dc * 32 + dd) * N_EMBED + j];
            s += v * v;
        }
    }
    red[dc][jl] = s;
    __syncthreads();
    if (dc == 0) {
        float t = red[0][jl] + red[1][jl] + red[2][jl] + red[3][jl];
        g_cnorm[j] = (j < N_EMBED) ? t : -1e30f;
    }
}

__device__ __forceinline__ void fma2(u64& d, u64 a, u64 b) {
    asm("fma.rn.f32x2 %0, %1, %2, %0;" : "+l"(d) : "l"(a), "l"(b));
}
__device__ __forceinline__ u64 dup2(float v) {
    u64 r; asm("mov.b64 %0, {%1, %1};" : "=l"(r) : "f"(v)); return r;
}
__device__ __forceinline__ float lo_f(u64 v) { return __uint_as_float((unsigned)v); }
__device__ __forceinline__ float hi_f(u64 v) { return __uint_as_float((unsigned)(v >> 32)); }
__device__ __forceinline__ unsigned smem_u32(const void* p) {
    return (unsigned)__cvta_generic_to_shared(p);
}
__device__ __forceinline__ void cp16(unsigned dst, const void* src, int sz) {
    asm volatile("cp.async.cg.shared.global [%0], [%1], 16, %2;"
                 :: "r"(dst), "l"(src), "r"(sz));
}
// Order-preserving encode: larger val -> larger u64; equal val -> smaller j wins.
__device__ __forceinline__ u64 enc_best(float v, int j) {
    unsigned b = __float_as_uint(v);
    b = ((int)b < 0) ? ~b : (b | 0x80000000u);
    return ((u64)b << 32) | (unsigned)(~j);
}

// Fused GEMM(-2x.c, biased by |c|^2) + argmax. One (m-tile, j-slice) per CTA.
// 16 warps; warp tile: 8 samples x 4 cols (lanes span 128 cols).
__global__ __launch_bounds__(THREADS, 1)
void quantize_kernel(const float* __restrict__ A,
                     const float* __restrict__ Bm) {
    extern __shared__ float smf[];
    float* As = smf;                 // [DIM][TM]  transposed, holds -2*x   64KB
    float* Bs = smf + DIM * TM;      // 2 x [DIM][TN] ring                 128KB

    const int tid  = threadIdx.x;
    const int lane = tid & 31;
    const int sy   = tid >> 5;       // warp -> 8-sample group (16 warps)
    const int mt   = blockIdx.x & 63;
    const int sl   = blockIdx.x >> 6;
    const int m0   = mt * TM;
    const int j00  = sl * SLICE_W;

    auto issueB = [&](int t) {
        const int j0 = j00 + t * TN;
        float* dst = Bs + (t & 1) * DIM * TN;
        for (int i = tid; i < DIM * (TN / 4); i += THREADS) {  // 8 iters
            int r  = i >> 5;        // 0..127
            int c4 = i & 31;        // 0..31
            int j  = j0 + 4 * c4;
            const float* src = (j < N_EMBED) ? (Bm + (size_t)r * N_EMBED + j) : Bm;
            cp16(smem_u32(dst + r * TN + 4 * c4), src, (j < N_EMBED) ? 16 : 0);
        }
        asm volatile("cp.async.commit_group;");
    };

    // Start B streaming first so it overlaps the A transpose below.
    issueB(0);
    issueB(1);

    // A tile: transpose into smem with -2 folded in.
    for (int i = tid; i < TM * (DIM / 4); i += THREADS) {  // 8 iters
        int k4 = i >> 7;             // 0..31
        int m  = i & 127;            // 0..127
        float4 v = *(const float4*)&A[(m0 + m) * DIM + 4 * k4];
        As[(4 * k4 + 0) * TM + m] = -2.f * v.x;
        As[(4 * k4 + 1) * TM + m] = -2.f * v.y;
        As[(4 * k4 + 2) * TM + m] = -2.f * v.z;
        As[(4 * k4 + 3) * TM + m] = -2.f * v.w;
    }

    float best[8];
    int   bestj[8];
#pragma unroll
    for (int i = 0; i < 8; i++) { best[i] = -FLT_MAX; bestj[i] = 0; }

    const float* Ap = As + 8 * sy;   // warp-uniform -> broadcast LDS

    for (int t = 0; t < NCH; t++) {
        if (t < NCH - 1) asm volatile("cp.async.wait_group 1;");
        else             asm volatile("cp.async.wait_group 0;");
        __syncthreads();             // chunk t resident; As complete (t==0)

        const float* Bp = Bs + (t & 1) * DIM * TN + 4 * lane;
        const int jbase = j00 + t * TN + 4 * lane;

        // acc starts at |c_j|^2 (same for both packed samples of a pair).
        float4 cn4 = *(const float4*)&g_cnorm[jbase];
        u64 cc[4] = {dup2(cn4.x), dup2(cn4.y), dup2(cn4.z), dup2(cn4.w)};
        u64 acc[4][4];
#pragma unroll
        for (int p = 0; p < 4; p++)
#pragma unroll
            for (int c = 0; c < 4; c++) acc[p][c] = cc[c];

#pragma unroll 4
        for (int k = 0; k < DIM; k++) {
            const ulonglong2* ap = (const ulonglong2*)(Ap + k * TM);
            ulonglong2 aa0 = ap[0];   // sample pairs (0,1),(2,3)
            ulonglong2 aa1 = ap[1];   // (4,5),(6,7)
            float4 b4 = *(const float4*)(Bp + k * TN);
            u64 b0 = dup2(b4.x), b1 = dup2(b4.y), b2 = dup2(b4.z), b3 = dup2(b4.w);
            u64 a[4] = {aa0.x, aa0.y, aa1.x, aa1.y};
#pragma unroll
            for (int p = 0; p < 4; p++) {
                fma2(acc[p][0], a[p], b0);
                fma2(acc[p][1], a[p], b1);
                fma2(acc[p][2], a[p], b2);
                fma2(acc[p][3], a[p], b3);
            }
        }

        // Running argmax. Ascending j + strict '>' keeps first-occurrence.
#pragma unroll
        for (int c = 0; c < 4; c++) {
#pragma unroll
            for (int p = 0; p < 4; p++) {
                float vlo = lo_f(acc[p][c]);
                float vhi = hi_f(acc[p][c]);
                int slo = 2 * p, shi = 2 * p + 1;
                if (vlo > best[slo]) { best[slo] = vlo; bestj[slo] = jbase + c; }
                if (vhi > best[shi]) { best[shi] = vhi; bestj[shi] = jbase + c; }
            }
        }

        __syncthreads();             // all warps done with slot (t&1)
        if (t + 2 < NCH) issueB(t + 2);
    }

    // Cross-lane argmax reduce (tie-break: smaller index), then global merge.
#pragma unroll
    for (int i = 0; i < 8; i++) {
        float v  = best[i];
        int   bj = bestj[i];
#pragma unroll
        for (int off = 16; off > 0; off >>= 1) {
            float v2 = __shfl_xor_sync(0xFFFFFFFFu, v, off);
            int   j2 = __shfl_xor_sync(0xFFFFFFFFu, bj, off);
            if (v2 > v || (v2 == v && j2 < bj)) { v = v2; bj = j2; }
        }
        if (lane == 0)
            atomicMax(&g_best[m0 + 8 * sy + i], enc_best(v, bj));
    }
}

// Merge results: gather quantize vector, write index + per-row MSE.
__global__ void combine_kernel(const float* __restrict__ A,
                               const float* __restrict__ Bm,
                               float* __restrict__ out) {
    const int w = threadIdx.x >> 5, lane = threadIdx.x & 31;
    const int s = blockIdx.x * 8 + w;
    const int j = (int)(unsigned)(~(unsigned)g_best[s]);
    float sum = 0.f;
#pragma unroll
    for (int r = 0; r < 4; r++) {
        const int d = lane + r * 32;
        float q = __ldg(&Bm[d * N_EMBED + j]);
        out[s * DIM + d] = q;
        float x = A[s * DIM + d];
        float t = x - q;
        sum += t * t;
    }
#pragma unroll
    for (int off = 16; off > 0; off >>= 1)
        sum += __shfl_xor_sync(0xFFFFFFFFu, sum, off);
    if (lane == 0) {
        out[N_SAMPLES * DIM + s] = (float)j;
        out[N_SAMPLES * (DIM + 1) + s] = sum * (1.0f / DIM);
    }
}

extern "C" void kernel_launch(void* const* d_in, const int* in_sizes, int n_in,
                              void* d_out, int out_size) {
    const float* A  = (const float*)d_in[0];   // inputs [8192,128]
    const float* Bm = (const float*)d_in[1];   // cluster_mean [128,10000]
    if (n_in >= 2 && in_sizes[0] == DIM * N_EMBED) {  // defensive order check
        const float* t = A; A = Bm; Bm = t;
    }
    float* out = (float*)d_out;

    cnorm_kernel<<<N_EMBED_PAD / 64, 256>>>(Bm);

    const int smem_bytes = (DIM * TM + 2 * DIM * TN) * (int)sizeof(float); // 192KB
    static int attr_set = 0;
    if (!attr_set) {
        cudaFuncSetAttribute(quantize_kernel,
                             cudaFuncAttributeMaxDynamicSharedMemorySize, smem_bytes);
        attr_set = 1;
    }
    quantize_kernel<<<64 * NSLICE, THREADS, smem_bytes>>>(A, Bm);
    combine_kernel<<<N_SAMPLES / 8, 256>>>(A, Bm, out);
}

// round 7
// speedup vs baseline: 1.0228x; 1.0228x over previous
#include <cuda_runtime.h>
#include <float.h>
#include <stdint.h>

#define N_SAMPLES 8192
#define DIM 128
#define N_EMBED 10000
#define N_EMBED_PAD 10240
#define TN 128
#define TM 128
#define THREADS 256
#define NSLICE 16
#define SLICE_W 640           // clusters per slice
#define NCH 5                 // chunks of TN per slice

typedef unsigned long long u64;

// Padded cluster norms; entries >= N_EMBED are -1e30 so they never win argmax.
__device__ float g_cnorm[N_EMBED_PAD];
// Per-sample packed (encoded_val << 32 | ~j); atomicMax-merged across slices.
__device__ u64 g_best[N_SAMPLES];

// 160 blocks x 256 threads: 64 j's per block, 4-way d-split + smem reduce.
__global__ void cnorm_kernel(const float* __restrict__ cm) {
    __shared__ float red[4][64];
    const int tid = threadIdx.x;
    const int jl  = tid & 63;
    const int dc  = tid >> 6;            // 0..3 -> d range [32*dc, 32*dc+32)
    const int j   = blockIdx.x * 64 + jl;

    const int gid = blockIdx.x * 256 + tid;
    if (gid < N_SAMPLES) g_best[gid] = 0ull;

    float s = 0.f;
    if (j < N_EMBED) {
#pragma unroll 8
        for (int dd = 0; dd < 32; dd++) {
            float v = cm[(dc * 32 + dd) * N_EMBED + j];
            s += v * v;
        }
    }
    red[dc][jl] = s;
    __syncthreads();
    if (dc == 0) {
        float t = red[0][jl] + red[1][jl] + red[2][jl] + red[3][jl];
        g_cnorm[j] = (j < N_EMBED) ? t : -1e30f;
    }
}

__device__ __forceinline__ void fma2(u64& d, u64 a, u64 b) {
    asm("fma.rn.f32x2 %0, %1, %2, %0;" : "+l"(d) : "l"(a), "l"(b));
}
__device__ __forceinline__ u64 dup2(float v) {
    u64 r; asm("mov.b64 %0, {%1, %1};" : "=l"(r) : "f"(v)); return r;
}
__device__ __forceinline__ float lo_f(u64 v) { return __uint_as_float((unsigned)v); }
__device__ __forceinline__ float hi_f(u64 v) { return __uint_as_float((unsigned)(v >> 32)); }
__device__ __forceinline__ unsigned smem_u32(const void* p) {
    return (unsigned)__cvta_generic_to_shared(p);
}
__device__ __forceinline__ void cp16(unsigned dst, const void* src, int sz) {
    asm volatile("cp.async.cg.shared.global [%0], [%1], 16, %2;"
                 :: "r"(dst), "l"(src), "r"(sz));
}
// Order-preserving encode: larger val -> larger u64; equal val -> smaller j wins.
__device__ __forceinline__ u64 enc_best(float v, int j) {
    unsigned b = __float_as_uint(v);
    b = ((int)b < 0) ? ~b : (b | 0x80000000u);
    return ((u64)b << 32) | (unsigned)(~j);
}

// Fused GEMM(-2x.c, biased by |c|^2) + argmax. One (m-tile, j-slice) per CTA.
// 8 warps; warp tile: 16 samples x 4 cols (lanes span 128 cols).
__global__ __launch_bounds__(THREADS, 1)
void quantize_kernel(const float* __restrict__ A,
                     const float* __restrict__ Bm) {
    extern __shared__ float smf[];
    float* As = smf;                 // [DIM][TM]  transposed, holds -2*x   64KB
    float* Bs = smf + DIM * TM;      // 2 x [DIM][TN] ring                 128KB

    const int tid  = threadIdx.x;
    const int lane = tid & 31;
    const int sy   = tid >> 5;       // warp -> 16-sample group (8 warps)
    const int mt   = blockIdx.x & 63;
    const int sl   = blockIdx.x >> 6;
    const int m0   = mt * TM;
    const int j00  = sl * SLICE_W;

    auto issueB = [&](int t) {
        const int j0 = j00 + t * TN;
        float* dst = Bs + (t & 1) * DIM * TN;
        for (int i = tid; i < DIM * (TN / 4); i += THREADS) {  // 16 iters
            int r  = i >> 5;        // 0..127
            int c4 = i & 31;        // 0..31
            int j  = j0 + 4 * c4;
            const float* src = (j < N_EMBED) ? (Bm + (size_t)r * N_EMBED + j) : Bm;
            cp16(smem_u32(dst + r * TN + 4 * c4), src, (j < N_EMBED) ? 16 : 0);
        }
        asm volatile("cp.async.commit_group;");
    };

    // Start B streaming first so it overlaps the A transpose below.
    issueB(0);
    issueB(1);

    // A tile: transpose into smem with -2 folded in.
    for (int i = tid; i < TM * (DIM / 4); i += THREADS) {  // 16 iters
        int k4 = i >> 7;             // 0..31
        int m  = i & 127;            // 0..127
        float4 v = *(const float4*)&A[(m0 + m) * DIM + 4 * k4];
        As[(4 * k4 + 0) * TM + m] = -2.f * v.x;
        As[(4 * k4 + 1) * TM + m] = -2.f * v.y;
        As[(4 * k4 + 2) * TM + m] = -2.f * v.z;
        As[(4 * k4 + 3) * TM + m] = -2.f * v.w;
    }

    float best[16];
    int   bestj[16];
#pragma unroll
    for (int i = 0; i < 16; i++) { best[i] = -FLT_MAX; bestj[i] = 0; }

    const float* Ap = As + 16 * sy;  // warp-uniform -> broadcast LDS

    for (int t = 0; t < NCH; t++) {
        if (t < NCH - 1) asm volatile("cp.async.wait_group 1;");
        else             asm volatile("cp.async.wait_group 0;");
        __syncthreads();             // chunk t resident; As complete (t==0)

        const float* Bp = Bs + (t & 1) * DIM * TN + 4 * lane;
        const int jbase = j00 + t * TN + 4 * lane;

        // acc starts at |c_j|^2 (same for both packed samples of a pair).
        float4 cn4 = *(const float4*)&g_cnorm[jbase];
        u64 cc[4] = {dup2(cn4.x), dup2(cn4.y), dup2(cn4.z), dup2(cn4.w)};
        u64 acc[8][4];
#pragma unroll
        for (int p = 0; p < 8; p++)
#pragma unroll
            for (int c = 0; c < 4; c++) acc[p][c] = cc[c];

        // Software-pipelined k-loop: loads for k+1 issued before compute of k.
        const float* ApK = Ap;
        const float* BpK = Bp;
        ulonglong2 x0 = ((const ulonglong2*)ApK)[0];
        ulonglong2 x1 = ((const ulonglong2*)ApK)[1];
        ulonglong2 x2 = ((const ulonglong2*)ApK)[2];
        ulonglong2 x3 = ((const ulonglong2*)ApK)[3];
        float4     xb = *(const float4*)BpK;

#pragma unroll 8
        for (int k = 0; k < DIM; k++) {
            ulonglong2 aa0 = x0, aa1 = x1, aa2 = x2, aa3 = x3;
            float4 b4 = xb;
            if (k + 1 < DIM) {
                ApK += TM; BpK += TN;
                x0 = ((const ulonglong2*)ApK)[0];
                x1 = ((const ulonglong2*)ApK)[1];
                x2 = ((const ulonglong2*)ApK)[2];
                x3 = ((const ulonglong2*)ApK)[3];
                xb = *(const float4*)BpK;
            }
            u64 b0 = dup2(b4.x), b1 = dup2(b4.y), b2 = dup2(b4.z), b3 = dup2(b4.w);
            u64 a[8] = {aa0.x, aa0.y, aa1.x, aa1.y, aa2.x, aa2.y, aa3.x, aa3.y};
#pragma unroll
            for (int p = 0; p < 8; p++) {
                fma2(acc[p][0], a[p], b0);
                fma2(acc[p][1], a[p], b1);
                fma2(acc[p][2], a[p], b2);
                fma2(acc[p][3], a[p], b3);
            }
        }

        // Running argmax. Ascending j + strict '>' keeps first-occurrence.
#pragma unroll
        for (int c = 0; c < 4; c++) {
#pragma unroll
            for (int p = 0; p < 8; p++) {
                float vlo = lo_f(acc[p][c]);
                float vhi = hi_f(acc[p][c]);
                int slo = 2 * p, shi = 2 * p + 1;
                if (vlo > best[slo]) { best[slo] = vlo; bestj[slo] = jbase + c; }
                if (vhi > best[shi]) { best[shi] = vhi; bestj[shi] = jbase + c; }
            }
        }

        __syncthreads();             // all warps done with slot (t&1)
        if (t + 2 < NCH) issueB(t + 2);
    }

    // Cross-lane argmax reduce (tie-break: smaller index), then global merge.
#pragma unroll
    for (int i = 0; i < 16; i++) {
        float v  = best[i];
        int   bj = bestj[i];
#pragma unroll
        for (int off = 16; off > 0; off >>= 1) {
            float v2 = __shfl_xor_sync(0xFFFFFFFFu, v, off);
            int   j2 = __shfl_xor_sync(0xFFFFFFFFu, bj, off);
            if (v2 > v || (v2 == v && j2 < bj)) { v = v2; bj = j2; }
        }
        if (lane == 0)
            atomicMax(&g_best[m0 + 16 * sy + i], enc_best(v, bj));
    }
}

// Merge results: gather quantize vector, write index + per-row MSE.
__global__ void combine_kernel(const float* __restrict__ A,
                               const float* __restrict__ Bm,
                               float* __restrict__ out) {
    const int w = threadIdx.x >> 5, lane = threadIdx.x & 31;
    const int s = blockIdx.x * 8 + w;
    const int j = (int)(unsigned)(~(unsigned)g_best[s]);
    float sum = 0.f;
#pragma unroll
    for (int r = 0; r < 4; r++) {
        const int d = lane + r * 32;
        float q = __ldg(&Bm[d * N_EMBED + j]);
        out[s * DIM + d] = q;
        float x = A[s * DIM + d];
        float t = x - q;
        sum += t * t;
    }
#pragma unroll
    for (int off = 16; off > 0; off >>= 1)
        sum += __shfl_xor_sync(0xFFFFFFFFu, sum, off);
    if (lane == 0) {
        out[N_SAMPLES * DIM + s] = (float)j;
        out[N_SAMPLES * (DIM + 1) + s] = sum * (1.0f / DIM);
    }
}

extern "C" void kernel_launch(void* const* d_in, const int* in_sizes, int n_in,
                              void* d_out, int out_size) {
    const float* A  = (const float*)d_in[0];   // inputs [8192,128]
    const float* Bm = (const float*)d_in[1];   // cluster_mean [128,10000]
    if (n_in >= 2 && in_sizes[0] == DIM * N_EMBED) {  // defensive order check
        const float* t = A; A = Bm; Bm = t;
    }
    float* out = (float*)d_out;

    cnorm_kernel<<<N_EMBED_PAD / 64, 256>>>(Bm);

    const int smem_bytes = (DIM * TM + 2 * DIM * TN) * (int)sizeof(float); // 192KB
    static int attr_set = 0;
    if (!attr_set) {
        cudaFuncSetAttribute(quantize_kernel,
                             cudaFuncAttributeMaxDynamicSharedMemorySize, smem_bytes);
        attr_set = 1;
    }
    quantize_kernel<<<64 * NSLICE, THREADS, smem_bytes>>>(A, Bm);
    combine_kernel<<<N_SAMPLES / 8, 256>>>(A, Bm, out);
}

// round 8
// speedup vs baseline: 1.0893x; 1.0650x over previous
#include <cuda_runtime.h>
#include <float.h>
#include <stdint.h>

#define DIM 128
#define N_SAMPLES 8192
#define N_EMBED 10000
#define N_EMBED_PAD 10240
#define TM 64
#define TN 64
#define BSTRIDE 72            // 64 + 8 pad: all 32 B-frag lanes hit distinct banks
#define THREADS 256
#define NSLICE 10
#define SLICE_W 1024
#define NCH 16                // chunks of TN per slice

typedef unsigned long long u64;

__device__ float g_cnorm[N_EMBED_PAD];          // |c_j|^2, -1e30 for pad
__device__ u64   g_best[N_SAMPLES];             // packed (enc(val)<<32 | ~j)
__device__ float g_bhi[DIM * N_EMBED_PAD];      // tf32 hi of cluster_mean
__device__ float g_blo[DIM * N_EMBED_PAD];      // tf32 lo residual

__device__ __forceinline__ uint32_t tf32_rna(float v) {
    uint32_t u; asm("cvt.rna.tf32.f32 %0, %1;" : "=r"(u) : "f"(v)); return u;
}
__device__ __forceinline__ unsigned smem_u32(const void* p) {
    return (unsigned)__cvta_generic_to_shared(p);
}
__device__ __forceinline__ void cp16(unsigned dst, const void* src) {
    asm volatile("cp.async.cg.shared.global [%0], [%1], 16;"
                 :: "r"(dst), "l"(src));
}
// Order-preserving encode: larger val -> larger u64; equal val -> smaller j wins.
__device__ __forceinline__ u64 enc_best(float v, int j) {
    unsigned b = __float_as_uint(v);
    b = ((int)b < 0) ? ~b : (b | 0x80000000u);
    return ((u64)b << 32) | (unsigned)(~j);
}
// D(16x8,f32) += A(16x8,tf32,row) * B(8x8,tf32,col)
__device__ __forceinline__ void mma_tf32(float* d, float4 a, float b0, float b1) {
    asm volatile(
        "mma.sync.aligned.m16n8k8.row.col.f32.tf32.tf32.f32 "
        "{%0,%1,%2,%3}, {%4,%5,%6,%7}, {%8,%9}, {%0,%1,%2,%3};"
        : "+f"(d[0]), "+f"(d[1]), "+f"(d[2]), "+f"(d[3])
        : "r"(__float_as_uint(a.x)), "r"(__float_as_uint(a.y)),
          "r"(__float_as_uint(a.z)), "r"(__float_as_uint(a.w)),
          "r"(__float_as_uint(b0)),  "r"(__float_as_uint(b1)));
}

// ---------------- prep kernels ----------------
__global__ void cnorm_kernel(const float* __restrict__ cm) {
    __shared__ float red[4][64];
    const int tid = threadIdx.x;
    const int jl  = tid & 63;
    const int dc  = tid >> 6;
    const int j   = blockIdx.x * 64 + jl;
    const int gid = blockIdx.x * 256 + tid;
    if (gid < N_SAMPLES) g_best[gid] = 0ull;
    float s = 0.f;
    if (j < N_EMBED) {
#pragma unroll 8
        for (int dd = 0; dd < 32; dd++) {
            float v = cm[(dc * 32 + dd) * N_EMBED + j];
            s += v * v;
        }
    }
    red[dc][jl] = s;
    __syncthreads();
    if (dc == 0) {
        float t = red[0][jl] + red[1][jl] + red[2][jl] + red[3][jl];
        g_cnorm[j] = (j < N_EMBED) ? t : -1e30f;
    }
}

// Split cluster_mean into tf32 hi/lo, padded [DIM][N_EMBED_PAD] (zero pad).
__global__ void prep_b_kernel(const float* __restrict__ cm) {
    int idx = blockIdx.x * 256 + threadIdx.x;
    if (idx >= DIM * N_EMBED_PAD) return;
    int k = idx / N_EMBED_PAD, j = idx - k * N_EMBED_PAD;
    float v = (j < N_EMBED) ? cm[k * N_EMBED + j] : 0.f;
    float hf = __uint_as_float(tf32_rna(v));
    g_bhi[idx] = hf;
    g_blo[idx] = __uint_as_float(tf32_rna(v - hf));
}

// ---------------- main mma kernel ----------------
// smem: Ahi[4mt][16ks][32lane][4] 32KB | Alo 32KB | B ring 2 x (hi+lo 128xBSTRIDE)
#define AFRAG_FLOATS (4 * 16 * 32 * 4)
#define BHALF_FLOATS (128 * BSTRIDE)
#define SMEM_FLOATS  (2 * AFRAG_FLOATS + 2 * 2 * BHALF_FLOATS)

__global__ __launch_bounds__(THREADS, 1)
void quantize_kernel(const float* __restrict__ A) {
    extern __shared__ float smf[];
    float* Ahi  = smf;
    float* Alo  = smf + AFRAG_FLOATS;
    float* Bbuf = smf + 2 * AFRAG_FLOATS;

    const int tid  = threadIdx.x;
    const int lane = tid & 31;
    const int sy   = tid >> 5;           // 8 warps: 2 m-groups x 4 n-groups
    const int wm   = sy >> 2;            // 0..1
    const int wn   = sy & 3;             // 0..3
    const int n0w  = wn * 16;
    const int mtg0 = wm * 2;             // warp's first m16-tile (of 4 in CTA)

    const int mt  = blockIdx.x & 127;
    const int sl  = blockIdx.x >> 7;
    const int m0  = mt * TM;
    const int j00 = sl * SLICE_W;

    auto issueB = [&](int t) {
        const int j0 = j00 + t * TN;
        float* dst = Bbuf + (t & 1) * (2 * BHALF_FLOATS);
        for (int i = tid; i < 4096; i += THREADS) {   // 16 iters
            int sel = i >> 11;            // 0 = hi, 1 = lo
            int k   = (i >> 4) & 127;
            int jj  = (i & 15) * 4;
            const float* src = (sel ? g_blo : g_bhi)
                             + (size_t)k * N_EMBED_PAD + j0 + jj;
            cp16(smem_u32(dst + sel * BHALF_FLOATS + k * BSTRIDE + jj), src);
        }
        asm volatile("cp.async.commit_group;");
    };

    issueB(0);
    issueB(1);

    // A prep: split -2x into tf32 hi/lo, fragment-major (1 LDS.128 per frag).
    for (int i = tid; i < 2048; i += THREADS) {      // 8 iters
        int li = i & 31;
        int ks = (i >> 5) & 15;
        int mq = i >> 9;                  // m16-tile 0..3
        int r = li >> 2, c = li & 3;
        int row = m0 + mq * 16 + r;
        int col = ks * 8 + c;
        float v0 = -2.f * A[row * DIM + col];
        float v1 = -2.f * A[(row + 8) * DIM + col];
        float v2 = -2.f * A[row * DIM + col + 4];
        float v3 = -2.f * A[(row + 8) * DIM + col + 4];
        float h0 = __uint_as_float(tf32_rna(v0));
        float h1 = __uint_as_float(tf32_rna(v1));
        float h2 = __uint_as_float(tf32_rna(v2));
        float h3 = __uint_as_float(tf32_rna(v3));
        int base = ((mq * 16 + ks) * 32 + li) * 4;
        *(float4*)&Ahi[base] = make_float4(h0, h1, h2, h3);
        *(float4*)&Alo[base] = make_float4(
            __uint_as_float(tf32_rna(v0 - h0)), __uint_as_float(tf32_rna(v1 - h1)),
            __uint_as_float(tf32_rna(v2 - h2)), __uint_as_float(tf32_rna(v3 - h3)));
    }

    float best[4];
    int   bestj[4];
#pragma unroll
    for (int i = 0; i < 4; i++) { best[i] = -FLT_MAX; bestj[i] = 0; }

    const int brow = lane & 3;           // B frag k-offset
    const int bcol = lane >> 2;          // B frag n-offset

    for (int t = 0; t < NCH; t++) {
        if (t < NCH - 1) asm volatile("cp.async.wait_group 1;");
        else             asm volatile("cp.async.wait_group 0;");
        __syncthreads();                 // chunk t + A frags resident

        const float* bh = Bbuf + (t & 1) * (2 * BHALF_FLOATS);
        const float* bl = bh + BHALF_FLOATS;
        const int j0 = j00 + t * TN;

        // acc[mt][nt][4], initialized with cnorm (cols: 2*(lane&3)+{0,1}).
        float acc[2][2][4];
#pragma unroll
        for (int nt = 0; nt < 2; nt++) {
            int c0 = j0 + n0w + nt * 8 + 2 * (lane & 3);
            float cn0 = __ldg(&g_cnorm[c0]);
            float cn1 = __ldg(&g_cnorm[c0 + 1]);
#pragma unroll
            for (int mq = 0; mq < 2; mq++) {
                acc[mq][nt][0] = cn0; acc[mq][nt][1] = cn1;
                acc[mq][nt][2] = cn0; acc[mq][nt][3] = cn1;
            }
        }

#pragma unroll 8
        for (int ks = 0; ks < 16; ks++) {
            float4 ah0 = *(const float4*)&Ahi[(((mtg0 + 0) * 16 + ks) * 32 + lane) * 4];
            float4 ah1 = *(const float4*)&Ahi[(((mtg0 + 1) * 16 + ks) * 32 + lane) * 4];
            float4 al0 = *(const float4*)&Alo[(((mtg0 + 0) * 16 + ks) * 32 + lane) * 4];
            float4 al1 = *(const float4*)&Alo[(((mtg0 + 1) * 16 + ks) * 32 + lane) * 4];
            int kr = ks * 8 + brow;
            float bh00 = bh[kr * BSTRIDE + n0w + bcol];
            float bh01 = bh[(kr + 4) * BSTRIDE + n0w + bcol];
            float bh10 = bh[kr * BSTRIDE + n0w + 8 + bcol];
            float bh11 = bh[(kr + 4) * BSTRIDE + n0w + 8 + bcol];
            float bl00 = bl[kr * BSTRIDE + n0w + bcol];
            float bl01 = bl[(kr + 4) * BSTRIDE + n0w + bcol];
            float bl10 = bl[kr * BSTRIDE + n0w + 8 + bcol];
            float bl11 = bl[(kr + 4) * BSTRIDE + n0w + 8 + bcol];

            mma_tf32(acc[0][0], ah0, bh00, bh01);
            mma_tf32(acc[1][0], ah1, bh00, bh01);
            mma_tf32(acc[0][1], ah0, bh10, bh11);
            mma_tf32(acc[1][1], ah1, bh10, bh11);
            mma_tf32(acc[0][0], al0, bh00, bh01);
            mma_tf32(acc[1][0], al1, bh00, bh01);
            mma_tf32(acc[0][1], al0, bh10, bh11);
            mma_tf32(acc[1][1], al1, bh10, bh11);
            mma_tf32(acc[0][0], ah0, bl00, bl01);
            mma_tf32(acc[1][0], ah1, bl00, bl01);
            mma_tf32(acc[0][1], ah0, bl10, bl11);
            mma_tf32(acc[1][1], ah1, bl10, bl11);
        }

        // Running argmax. nt ascending + col0<col1 keeps ascending-j scan.
#pragma unroll
        for (int nt = 0; nt < 2; nt++) {
            int c0 = j0 + n0w + nt * 8 + 2 * (lane & 3);
#pragma unroll
            for (int mq = 0; mq < 2; mq++) {
#pragma unroll
                for (int rb = 0; rb < 2; rb++) {
                    int slot = mq * 2 + rb;
                    float v0 = acc[mq][nt][rb * 2 + 0];
                    float v1 = acc[mq][nt][rb * 2 + 1];
                    if (v0 > best[slot]) { best[slot] = v0; bestj[slot] = c0; }
                    if (v1 > best[slot]) { best[slot] = v1; bestj[slot] = c0 + 1; }
                }
            }
        }

        __syncthreads();                 // all warps done with slot (t&1)
        if (t + 2 < NCH) issueB(t + 2);
    }

    // Reduce across the 4 lanes of each quad (same rows), then global merge.
#pragma unroll
    for (int s = 0; s < 4; s++) {
        float v  = best[s];
        int   bj = bestj[s];
#pragma unroll
        for (int off = 1; off < 4; off <<= 1) {
            float v2 = __shfl_xor_sync(0xFFFFFFFFu, v, off);
            int   j2 = __shfl_xor_sync(0xFFFFFFFFu, bj, off);
            if (v2 > v || (v2 == v && j2 < bj)) { v = v2; bj = j2; }
        }
        if ((lane & 3) == 0) {
            int mq = s >> 1, rb = s & 1;
            int row = m0 + (mtg0 + mq) * 16 + (lane >> 2) + rb * 8;
            atomicMax(&g_best[row], enc_best(v, bj));
        }
    }
}

// Merge results: gather quantize vector, write index + per-row MSE.
__global__ void combine_kernel(const float* __restrict__ A,
                               const float* __restrict__ Bm,
                               float* __restrict__ out) {
    const int w = threadIdx.x >> 5, lane = threadIdx.x & 31;
    const int s = blockIdx.x * 8 + w;
    const int j = (int)(unsigned)(~(unsigned)g_best[s]);
    float sum = 0.f;
#pragma unroll
    for (int r = 0; r < 4; r++) {
        const int d = lane + r * 32;
        float q = __ldg(&Bm[d * N_EMBED + j]);
        out[s * DIM + d] = q;
        float x = A[s * DIM + d];
        float t = x - q;
        sum += t * t;
    }
#pragma unroll
    for (int off = 16; off > 0; off >>= 1)
        sum += __shfl_xor_sync(0xFFFFFFFFu, sum, off);
    if (lane == 0) {
        out[N_SAMPLES * DIM + s] = (float)j;
        out[N_SAMPLES * (DIM + 1) + s] = sum * (1.0f / DIM);
    }
}

extern "C" void kernel_launch(void* const* d_in, const int* in_sizes, int n_in,
                              void* d_out, int out_size) {
    const float* A  = (const float*)d_in[0];   // inputs [8192,128]
    const float* Bm = (const float*)d_in[1];   // cluster_mean [128,10000]
    if (n_in >= 2 && in_sizes[0] == DIM * N_EMBED) {  // defensive order check
        const float* t = A; A = Bm; Bm = t;
    }
    float* out = (float*)d_out;

    cnorm_kernel<<<N_EMBED_PAD / 64, 256>>>(Bm);
    prep_b_kernel<<<DIM * N_EMBED_PAD / 256, 256>>>(Bm);

    const int smem_bytes = SMEM_FLOATS * (int)sizeof(float);   // 208KB
    static int attr_set = 0;
    if (!attr_set) {
        cudaFuncSetAttribute(quantize_kernel,
                             cudaFuncAttributeMaxDynamicSharedMemorySize, smem_bytes);
        attr_set = 1;
    }
    quantize_kernel<<<128 * NSLICE, THREADS, smem_bytes>>>(A);
    combine_kernel<<<N_SAMPLES / 8, 256>>>(A, Bm, out);
}